// round 3
// baseline (speedup 1.0000x reference)
#include <cuda_runtime.h>

#define Bz 8
#define C  512
#define NH 8
#define HD 64
#define N  1024   /* 32*32 */
#define LOG2E 1.4426950408889634f

// Scratch: per-head q/k/v and attention output in (b,n,c) layout.
__device__ float g_q[Bz*NH*N*HD];
__device__ float g_k[Bz*NH*N*HD];
__device__ float g_v[Bz*NH*N*HD];
__device__ float g_ao[Bz*N*C];

// ---------------------------------------------------------------------------
// Kernel 1: qkv = x_seq @ W_qkv^T + b_qkv, scattered into g_q/g_k/g_v.
// x is (b, c, n) with n contiguous -> x_seq[n][c] read as A[c-tile][n-tile].
// Tile: 64(n) x 64(o) x 16(c). 256 threads, 4x4 per thread.
// ---------------------------------------------------------------------------
__global__ void qkv_kernel(const float* __restrict__ x,
                           const float* __restrict__ Wqkv,
                           const float* __restrict__ bqkv) {
    __shared__ __align__(16) float As[16][64];   // As[k][n]
    __shared__ __align__(16) float Bs2[16][64];  // Bs2[k][o]
    const int b  = blockIdx.z;
    const int n0 = blockIdx.x * 64;
    const int o0 = blockIdx.y * 64;
    const int tx = threadIdx.x, ty = threadIdx.y;
    const int t  = ty * 16 + tx;
    const float* xb = x + (size_t)b * C * N;

    float acc[4][4] = {};
    for (int k0 = 0; k0 < C; k0 += 16) {
        {   // A tile: 16 rows (c) x 64 cols (n), contiguous in n
            int kk = t >> 4, m4 = (t & 15) * 4;
            *(float4*)&As[kk][m4] = *(const float4*)&xb[(k0 + kk) * N + n0 + m4];
        }
        {   // B tile: W_qkv[o][c], transpose into Bs2[k][o]
            int oo = t >> 2, k4 = (t & 3) * 4;
            float4 v = *(const float4*)&Wqkv[(size_t)(o0 + oo) * C + k0 + k4];
            Bs2[k4 + 0][oo] = v.x; Bs2[k4 + 1][oo] = v.y;
            Bs2[k4 + 2][oo] = v.z; Bs2[k4 + 3][oo] = v.w;
        }
        __syncthreads();
        #pragma unroll
        for (int k = 0; k < 16; k++) {
            float4 a  = *(float4*)&As[k][ty * 4];
            float4 bb = *(float4*)&Bs2[k][tx * 4];
            float av[4] = {a.x, a.y, a.z, a.w};
            float bv[4] = {bb.x, bb.y, bb.z, bb.w};
            #pragma unroll
            for (int i = 0; i < 4; i++)
                #pragma unroll
                for (int j = 0; j < 4; j++)
                    acc[i][j] += av[i] * bv[j];
        }
        __syncthreads();
    }

    // o-tile (64-wide, 64-aligned) maps to exactly one (three, head) pair.
    const int three = o0 / 512;
    const int h     = (o0 % 512) / 64;
    float* dst = (three == 0 ? g_q : (three == 1 ? g_k : g_v))
               + (size_t)((b * NH + h) * N) * HD;
    #pragma unroll
    for (int i = 0; i < 4; i++) {
        int n  = n0 + ty * 4 + i;
        int d0 = tx * 4;
        float4 v;
        v.x = acc[i][0] + bqkv[o0 + d0 + 0];
        v.y = acc[i][1] + bqkv[o0 + d0 + 1];
        v.z = acc[i][2] + bqkv[o0 + d0 + 2];
        v.w = acc[i][3] + bqkv[o0 + d0 + 3];
        *(float4*)&dst[n * HD + d0] = v;
    }
}

// ---------------------------------------------------------------------------
// Kernel 2: causal flash attention. Block = 256 threads, 64 query rows.
// Phase 1 (16x16 threads, 4x4 each): S = scale * Q K^T into smem (+mask).
// Phase 2 (thread = (row, 16-wide d slice)): online softmax + O += P V.
// ---------------------------------------------------------------------------
extern __shared__ float sm_attn[];

__global__ void attn_kernel() {
    // Qt[64][68] (Qt[d][r]), Kt[64][68] (Kt[d][c]), Ss[64][65], Vs[64][68]
    float* Qt = sm_attn;
    float* Kt = Qt + 64 * 68;
    float* Ss = Kt + 64 * 68;
    float* Vs = Ss + 64 * 65;

    const int qt = blockIdx.x;
    const int bh = blockIdx.y;
    const int n0 = qt * 64;
    const float* Q = g_q + (size_t)bh * N * HD;
    const float* K = g_k + (size_t)bh * N * HD;
    const float* V = g_v + (size_t)bh * N * HD;

    const int t  = threadIdx.x;
    const int tx = t & 15, ty = t >> 4;
    const int r2 = t & 63, g2 = t >> 6;   // phase-2 mapping

    // Load Q tile transposed (once)
    #pragma unroll
    for (int it = 0; it < 4; it++) {
        int e = t * 4 + it * 1024;
        int r = e >> 6, d = e & 63;
        float4 v = *(const float4*)&Q[(n0 + r) * HD + d];
        Qt[(d + 0) * 68 + r] = v.x; Qt[(d + 1) * 68 + r] = v.y;
        Qt[(d + 2) * 68 + r] = v.z; Qt[(d + 3) * 68 + r] = v.w;
    }

    float m = -1e30f, l = 0.f;
    float Oacc[16];
    #pragma unroll
    for (int k = 0; k < 16; k++) Oacc[k] = 0.f;

    for (int kt = 0; kt <= qt; kt++) {
        const int k0 = kt * 64;
        __syncthreads();   // prev-iter Ss/Vs consumers done; also orders Qt stores
        #pragma unroll
        for (int it = 0; it < 4; it++) {
            int e = t * 4 + it * 1024;
            int r = e >> 6, d = e & 63;
            float4 v = *(const float4*)&K[(k0 + r) * HD + d];
            Kt[(d + 0) * 68 + r] = v.x; Kt[(d + 1) * 68 + r] = v.y;
            Kt[(d + 2) * 68 + r] = v.z; Kt[(d + 3) * 68 + r] = v.w;
            *(float4*)&Vs[r * 68 + d] = *(const float4*)&V[(k0 + r) * HD + d];
        }
        __syncthreads();

        // Phase 1: S tile
        float acc[4][4] = {};
        #pragma unroll
        for (int k = 0; k < 64; k++) {
            float4 a  = *(float4*)&Qt[k * 68 + ty * 4];
            float4 bb = *(float4*)&Kt[k * 68 + tx * 4];
            float av[4] = {a.x, a.y, a.z, a.w};
            float bv[4] = {bb.x, bb.y, bb.z, bb.w};
            #pragma unroll
            for (int i = 0; i < 4; i++)
                #pragma unroll
                for (int j = 0; j < 4; j++)
                    acc[i][j] += av[i] * bv[j];
        }
        #pragma unroll
        for (int i = 0; i < 4; i++) {
            int qi = n0 + ty * 4 + i;
            #pragma unroll
            for (int j = 0; j < 4; j++) {
                int kj = k0 + tx * 4 + j;
                float s = acc[i][j] * 0.125f;           // hd^-0.5 = 1/8
                if (kj > qi) s = -1e30f;                // causal mask
                Ss[(ty * 4 + i) * 65 + tx * 4 + j] = s;
            }
        }
        __syncthreads();

        // Phase 2: online softmax + PV
        const float* srow = &Ss[r2 * 65];
        float mloc = m;
        #pragma unroll 8
        for (int j = 0; j < 64; j++) mloc = fmaxf(mloc, srow[j]);
        float factor = exp2f((m - mloc) * LOG2E);
        m = mloc;
        l *= factor;
        #pragma unroll
        for (int k = 0; k < 16; k++) Oacc[k] *= factor;
        for (int j = 0; j < 64; j++) {
            float p = exp2f((srow[j] - m) * LOG2E);
            l += p;
            const float* vr = &Vs[j * 68 + g2 * 16];
            #pragma unroll
            for (int k = 0; k < 16; k++) Oacc[k] += p * vr[k];
        }
    }

    // Write (b, n, c) layout
    const float inv = 1.f / l;
    const int b = bh / NH, h = bh % NH;
    float* dst = g_ao + ((size_t)(b * N + n0 + r2)) * C + h * HD + g2 * 16;
    #pragma unroll
    for (int k = 0; k < 16; k += 4) {
        float4 v = {Oacc[k] * inv, Oacc[k + 1] * inv,
                    Oacc[k + 2] * inv, Oacc[k + 3] * inv};
        *(float4*)&dst[k] = v;
    }
}

// ---------------------------------------------------------------------------
// Kernel 3: out[b][co][n] = g_ao[b][n][:] @ W_proj[co][:] + b_proj[co]
// Tile: 64(co) x 64(n) x 16(c). Writes final (b, c, h, w) layout directly.
// ---------------------------------------------------------------------------
__global__ void proj_kernel(const float* __restrict__ Wp,
                            const float* __restrict__ bp,
                            float* __restrict__ out) {
    __shared__ __align__(16) float Ws[16][64];  // Ws[k][co]
    __shared__ __align__(16) float As[16][64];  // As[k][n]
    const int b  = blockIdx.z;
    const int n0 = blockIdx.x * 64;
    const int c0 = blockIdx.y * 64;
    const int tx = threadIdx.x, ty = threadIdx.y;
    const int t  = ty * 16 + tx;
    const float* A = g_ao + (size_t)b * N * C;

    float acc[4][4] = {};
    for (int k0 = 0; k0 < C; k0 += 16) {
        {
            int coo = t >> 2, k4 = (t & 3) * 4;
            float4 v = *(const float4*)&Wp[(size_t)(c0 + coo) * C + k0 + k4];
            Ws[k4 + 0][coo] = v.x; Ws[k4 + 1][coo] = v.y;
            Ws[k4 + 2][coo] = v.z; Ws[k4 + 3][coo] = v.w;
        }
        {
            int nn = t >> 2, k4 = (t & 3) * 4;
            float4 v = *(const float4*)&A[(size_t)(n0 + nn) * C + k0 + k4];
            As[k4 + 0][nn] = v.x; As[k4 + 1][nn] = v.y;
            As[k4 + 2][nn] = v.z; As[k4 + 3][nn] = v.w;
        }
        __syncthreads();
        #pragma unroll
        for (int k = 0; k < 16; k++) {
            float4 a  = *(float4*)&Ws[k][ty * 4];
            float4 bb = *(float4*)&As[k][tx * 4];
            float av[4] = {a.x, a.y, a.z, a.w};
            float bv[4] = {bb.x, bb.y, bb.z, bb.w};
            #pragma unroll
            for (int i = 0; i < 4; i++)
                #pragma unroll
                for (int j = 0; j < 4; j++)
                    acc[i][j] += av[i] * bv[j];
        }
        __syncthreads();
    }
    #pragma unroll
    for (int i = 0; i < 4; i++) {
        int co = c0 + ty * 4 + i;
        float bias = bp[co];
        float4 v = {acc[i][0] + bias, acc[i][1] + bias,
                    acc[i][2] + bias, acc[i][3] + bias};
        *(float4*)&out[((size_t)b * C + co) * N + n0 + tx * 4] = v;
    }
}

// ---------------------------------------------------------------------------
extern "C" void kernel_launch(void* const* d_in, const int* in_sizes, int n_in,
                              void* d_out, int out_size) {
    (void)in_sizes; (void)n_in; (void)out_size;
    const float* x    = (const float*)d_in[0];
    const float* Wqkv = (const float*)d_in[1];
    const float* bqkv = (const float*)d_in[2];
    const float* Wp   = (const float*)d_in[3];
    const float* bp   = (const float*)d_in[4];
    float* out = (float*)d_out;

    const int attn_smem = (64 * 68 * 3 + 64 * 65) * (int)sizeof(float); // 69,888 B
    cudaFuncSetAttribute(attn_kernel,
                         cudaFuncAttributeMaxDynamicSharedMemorySize, attn_smem);

    qkv_kernel<<<dim3(16, 24, Bz), dim3(16, 16)>>>(x, Wqkv, bqkv);
    attn_kernel<<<dim3(16, Bz * NH), 256, attn_smem>>>();
    proj_kernel<<<dim3(16, 8, Bz), dim3(16, 16)>>>(Wp, bp, out);
}

// round 4
// speedup vs baseline: 2.3845x; 2.3845x over previous
#include <cuda_runtime.h>
#include <cstdint>

#define Bz 8
#define C  512
#define NH 8
#define HD 64
#define N  1024   /* 32*32 */
#define LOG2E 1.4426950408889634f
#define SMSCALE (0.125f * LOG2E)   /* hd^-0.5 * log2(e) */

// Scratch: per-head q/k/v (b,h,n,d) and attention output TRANSPOSED (b,c,n).
__device__ float g_q[Bz*NH*N*HD];
__device__ float g_k[Bz*NH*N*HD];
__device__ float g_v[Bz*NH*N*HD];
__device__ float g_ao[Bz*C*N];     // aoT: [b][cfeat][n]

// ---------------------------------------------------------------------------
__device__ __forceinline__ uint32_t f2tf(float f) {
    uint32_t r;
    asm("cvt.rna.tf32.f32 %0, %1;" : "=r"(r) : "f"(f));
    return r;
}

__device__ __forceinline__ void mma8(float* c, const uint32_t* a, const uint32_t* b) {
    asm volatile(
        "mma.sync.aligned.m16n8k8.row.col.f32.tf32.tf32.f32 "
        "{%0,%1,%2,%3}, {%4,%5,%6,%7}, {%8,%9}, {%0,%1,%2,%3};"
        : "+f"(c[0]), "+f"(c[1]), "+f"(c[2]), "+f"(c[3])
        : "r"(a[0]), "r"(a[1]), "r"(a[2]), "r"(a[3]), "r"(b[0]), "r"(b[1]));
}

// ---------------------------------------------------------------------------
// Kernel 1: qkv = x_seq @ W_qkv^T + b_qkv  (M=n per batch, N=o=1536, K=c=512)
// Block tile 128(m) x 128(o), BK=16. 8 warps, warp tile 64x32, m16n8k8 tf32.
// Smem k-major, stride 136 words (conflict-free fragment reads).
// ---------------------------------------------------------------------------
__global__ __launch_bounds__(256) void qkv_kernel(const float* __restrict__ x,
                                                  const float* __restrict__ Wqkv,
                                                  const float* __restrict__ bqkv) {
    __shared__ uint32_t As[16 * 136];   // [k][m]
    __shared__ uint32_t Bs[16 * 136];   // [k][o]
    const int b  = blockIdx.z;
    const int n0 = blockIdx.x * 128;
    const int o0 = blockIdx.y * 128;
    const int t = threadIdx.x, w = t >> 5, lane = t & 31;
    const int g = lane >> 2, tg = lane & 3;
    const int wm = w & 1, wn = w >> 1;
    const float* xb = x + (size_t)b * C * N;

    float acc[4][4][4];
    #pragma unroll
    for (int i = 0; i < 4; i++)
        #pragma unroll
        for (int j = 0; j < 4; j++)
            #pragma unroll
            for (int r = 0; r < 4; r++) acc[i][j][r] = 0.f;

    for (int k0 = 0; k0 < C; k0 += 16) {
        #pragma unroll
        for (int s = 0; s < 2; s++) {   // A: direct rows (c-major), vectorized
            int jdx = t + s * 256;
            int kk = jdx >> 5, nn = (jdx & 31) * 4;
            float4 v = *(const float4*)&xb[(size_t)(k0 + kk) * N + n0 + nn];
            uint4 u = {f2tf(v.x), f2tf(v.y), f2tf(v.z), f2tf(v.w)};
            *(uint4*)&As[kk * 136 + nn] = u;
        }
        #pragma unroll
        for (int s = 0; s < 2; s++) {   // B: transpose W[o][c] -> Bs[k][o]
            int jdx = t + s * 256;
            int oo = jdx >> 2, k4 = (jdx & 3) * 4;
            float4 v = *(const float4*)&Wqkv[(size_t)(o0 + oo) * C + k0 + k4];
            Bs[(k4 + 0) * 136 + oo] = f2tf(v.x);
            Bs[(k4 + 1) * 136 + oo] = f2tf(v.y);
            Bs[(k4 + 2) * 136 + oo] = f2tf(v.z);
            Bs[(k4 + 3) * 136 + oo] = f2tf(v.w);
        }
        __syncthreads();
        #pragma unroll
        for (int ks = 0; ks < 2; ks++) {
            const int kk = ks * 8;
            uint32_t a[4][4], bb[4][2];
            #pragma unroll
            for (int i = 0; i < 4; i++) {
                const uint32_t* p = &As[(kk + tg) * 136 + wm * 64 + i * 16 + g];
                a[i][0] = p[0]; a[i][1] = p[8];
                a[i][2] = p[4 * 136]; a[i][3] = p[4 * 136 + 8];
            }
            #pragma unroll
            for (int j = 0; j < 4; j++) {
                const uint32_t* p = &Bs[(kk + tg) * 136 + wn * 32 + j * 8 + g];
                bb[j][0] = p[0]; bb[j][1] = p[4 * 136];
            }
            #pragma unroll
            for (int i = 0; i < 4; i++)
                #pragma unroll
                for (int j = 0; j < 4; j++) mma8(acc[i][j], a[i], bb[j]);
        }
        __syncthreads();
    }

    // Epilogue: scatter into g_q/g_k/g_v (b,h,n,d). o0 is 128-aligned -> one "three".
    const int three = o0 >> 9;
    float* base = (three == 0 ? g_q : (three == 1 ? g_k : g_v));
    #pragma unroll
    for (int j = 0; j < 4; j++) {
        const int o = o0 + wn * 32 + j * 8 + 2 * tg;
        const int h = (o >> 6) & 7, d = o & 63;
        const float b0v = bqkv[o], b1v = bqkv[o + 1];
        float* dsth = base + ((size_t)(b * NH + h) * N) * HD + d;
        #pragma unroll
        for (int i = 0; i < 4; i++) {
            const int n1 = n0 + wm * 64 + i * 16 + g;
            float2 v0 = {acc[i][j][0] + b0v, acc[i][j][1] + b1v};
            float2 v1 = {acc[i][j][2] + b0v, acc[i][j][3] + b1v};
            *(float2*)&dsth[(size_t)n1 * HD]       = v0;
            *(float2*)&dsth[(size_t)(n1 + 8) * HD] = v1;
        }
    }
}

// ---------------------------------------------------------------------------
// Kernel 2: causal flash attention with tf32 MMA.
// Block = 128 threads (4 warps), 64 query rows, 64-wide K tiles.
// Warp w owns rows [w*16, w*16+16). Phase1: S = QK^T (MMA). Smem softmax.
// Phase2: O += P V (MMA, accumulators persistent in registers).
// ---------------------------------------------------------------------------
extern __shared__ char sm_raw[];

__global__ __launch_bounds__(128) void attn_kernel() {
    uint32_t* Qs = (uint32_t*)sm_raw;       // [64][68] tf32, row q major
    uint32_t* Kt = Qs + 64 * 68;            // [64 d][68 kpos] tf32
    uint32_t* Vs = Kt + 64 * 68;            // [64 kpos][68 d] tf32
    float*    Sf = (float*)(Vs + 64 * 68);  // [64 q][68 kpos] raw logits
    uint32_t* Su = (uint32_t*)Sf;           // same storage, tf32(P) after exp
    float* mrow = (float*)(Sf + 64 * 68);   // [64]
    float* lrow = mrow + 64;                // [64]
    float* frow = lrow + 64;                // [64]
    float* pmax = frow + 64;                // [64][2]
    float* psum = pmax + 128;               // [64][2]

    const int qt = blockIdx.x, bh = blockIdx.y;
    const int n0 = qt * 64;
    const float* Q = g_q + (size_t)bh * N * HD;
    const float* K = g_k + (size_t)bh * N * HD;
    const float* V = g_v + (size_t)bh * N * HD;

    const int t = threadIdx.x, w = t >> 5, lane = t & 31;
    const int g = lane >> 2, tg = lane & 3;
    const int m0 = w * 16;

    // Q tile -> smem (tf32)
    #pragma unroll
    for (int it = 0; it < 8; it++) {
        int e = t * 4 + it * 512;
        int r = e >> 6, d = e & 63;
        float4 v = *(const float4*)&Q[(size_t)(n0 + r) * HD + d];
        uint4 u = {f2tf(v.x), f2tf(v.y), f2tf(v.z), f2tf(v.w)};
        *(uint4*)&Qs[r * 68 + d] = u;
    }
    if (t < 64) { mrow[t] = -1e30f; lrow[t] = 0.f; }

    float o[8][4];
    #pragma unroll
    for (int j = 0; j < 8; j++)
        #pragma unroll
        for (int r = 0; r < 4; r++) o[j][r] = 0.f;

    for (int kt = 0; kt <= qt; kt++) {
        const int k0 = kt * 64;
        const bool diag = (kt == qt);
        __syncthreads();   // guards Vs/Su reuse from previous iteration
        // K tile transposed: Kt[d][kpos]
        #pragma unroll
        for (int it = 0; it < 8; it++) {
            int r = (t & 7) + it * 8, d = (t >> 3) * 4;
            float4 v = *(const float4*)&K[(size_t)(k0 + r) * HD + d];
            Kt[(d + 0) * 68 + r] = f2tf(v.x);
            Kt[(d + 1) * 68 + r] = f2tf(v.y);
            Kt[(d + 2) * 68 + r] = f2tf(v.z);
            Kt[(d + 3) * 68 + r] = f2tf(v.w);
        }
        // V tile direct: Vs[kpos][d]
        #pragma unroll
        for (int it = 0; it < 8; it++) {
            int e = t * 4 + it * 512;
            int r = e >> 6, d = e & 63;
            float4 v = *(const float4*)&V[(size_t)(k0 + r) * HD + d];
            uint4 u = {f2tf(v.x), f2tf(v.y), f2tf(v.z), f2tf(v.w)};
            *(uint4*)&Vs[r * 68 + d] = u;
        }
        __syncthreads();

        // ---- Phase 1: S = Q K^T ----
        float s[8][4];
        #pragma unroll
        for (int j = 0; j < 8; j++)
            #pragma unroll
            for (int r = 0; r < 4; r++) s[j][r] = 0.f;
        #pragma unroll
        for (int ks = 0; ks < 8; ks++) {
            const int kk = ks * 8;
            uint32_t a[4];
            const uint32_t* pa = &Qs[(m0 + g) * 68 + kk + tg];
            a[0] = pa[0]; a[1] = pa[8 * 68]; a[2] = pa[4]; a[3] = pa[8 * 68 + 4];
            #pragma unroll
            for (int j = 0; j < 8; j++) {
                uint32_t bb[2];
                const uint32_t* pb = &Kt[(kk + tg) * 68 + j * 8 + g];
                bb[0] = pb[0]; bb[1] = pb[4 * 68];
                mma8(s[j], a, bb);
            }
        }
        #pragma unroll
        for (int j = 0; j < 8; j++) {
            float* p = &Sf[(m0 + g) * 68 + j * 8 + 2 * tg];
            p[0] = s[j][0]; p[1] = s[j][1];
            p[8 * 68] = s[j][2]; p[8 * 68 + 1] = s[j][3];
        }
        __syncthreads();

        // ---- Softmax: row max (thread = (row, half)) ----
        {
            const int r = t >> 1, hf = t & 1, cb = hf * 32;
            const int qg = n0 + r;
            const float* srow = &Sf[r * 68 + cb];
            float mx = -1e30f;
            #pragma unroll 8
            for (int c2 = 0; c2 < 32; c2++) {
                float v = srow[c2];
                if (diag && (k0 + cb + c2 > qg)) v = -1e30f;
                mx = fmaxf(mx, v);
            }
            pmax[r * 2 + hf] = mx;
        }
        __syncthreads();
        if (t < 64) {
            const float mx = fmaxf(pmax[t * 2], pmax[t * 2 + 1]) * SMSCALE;
            const float mold = mrow[t];
            const float mnew = fmaxf(mold, mx);
            frow[t] = exp2f(mold - mnew);
            mrow[t] = mnew;
        }
        __syncthreads();
        // ---- exp + P (tf32) in place ----
        {
            const int r = t >> 1, hf = t & 1, cb = hf * 32;
            const int qg = n0 + r;
            const float mr = mrow[r];
            float* srow = &Sf[r * 68 + cb];
            uint32_t* urow = &Su[r * 68 + cb];
            float sum = 0.f;
            #pragma unroll 8
            for (int c2 = 0; c2 < 32; c2++) {
                float p = exp2f(srow[c2] * SMSCALE - mr);
                if (diag && (k0 + cb + c2 > qg)) p = 0.f;
                sum += p;
                urow[c2] = f2tf(p);
            }
            psum[r * 2 + hf] = sum;
        }
        __syncthreads();
        if (t < 64) lrow[t] = lrow[t] * frow[t] + psum[t * 2] + psum[t * 2 + 1];

        // ---- Phase 2: O = O*factor + P V ----
        const float f0 = frow[m0 + g], f1 = frow[m0 + g + 8];
        #pragma unroll
        for (int j = 0; j < 8; j++) {
            o[j][0] *= f0; o[j][1] *= f0; o[j][2] *= f1; o[j][3] *= f1;
        }
        #pragma unroll
        for (int ks = 0; ks < 8; ks++) {
            const int kk = ks * 8;
            uint32_t a[4];
            const uint32_t* pa = &Su[(m0 + g) * 68 + kk + tg];
            a[0] = pa[0]; a[1] = pa[8 * 68]; a[2] = pa[4]; a[3] = pa[8 * 68 + 4];
            #pragma unroll
            for (int j = 0; j < 8; j++) {
                uint32_t bb[2];
                const uint32_t* pb = &Vs[(kk + tg) * 68 + j * 8 + g];
                bb[0] = pb[0]; bb[1] = pb[4 * 68];
                mma8(o[j], a, bb);
            }
        }
    }

    __syncthreads();   // lrow written by warps 0/1, read by all
    const float inv0 = 1.f / lrow[m0 + g], inv1 = 1.f / lrow[m0 + g + 8];
    const int b = bh >> 3, h = bh & 7;
    float* ao = g_ao + (size_t)b * C * N + (size_t)h * 64 * N;  // [cfeat][n]
    const int n1 = n0 + m0 + g;
    #pragma unroll
    for (int j = 0; j < 8; j++) {
        const int d = j * 8 + 2 * tg;
        ao[(size_t)d * N + n1]           = o[j][0] * inv0;
        ao[(size_t)(d + 1) * N + n1]     = o[j][1] * inv0;
        ao[(size_t)d * N + n1 + 8]       = o[j][2] * inv1;
        ao[(size_t)(d + 1) * N + n1 + 8] = o[j][3] * inv1;
    }
}

// ---------------------------------------------------------------------------
// Kernel 3: out[b][co][n] = aoT[b][:,n] @ W_proj[co][:] + b_proj[co]
// Same structure as qkv (A = aoT is c-major -> direct loads).
// ---------------------------------------------------------------------------
__global__ __launch_bounds__(256) void proj_kernel(const float* __restrict__ Wp,
                                                   const float* __restrict__ bp,
                                                   float* __restrict__ out) {
    __shared__ uint32_t As[16 * 136];
    __shared__ uint32_t Bs[16 * 136];
    const int b  = blockIdx.z;
    const int n0 = blockIdx.x * 128;
    const int c0 = blockIdx.y * 128;
    const int t = threadIdx.x, w = t >> 5, lane = t & 31;
    const int g = lane >> 2, tg = lane & 3;
    const int wm = w & 1, wn = w >> 1;
    const float* A = g_ao + (size_t)b * C * N;

    float acc[4][4][4];
    #pragma unroll
    for (int i = 0; i < 4; i++)
        #pragma unroll
        for (int j = 0; j < 4; j++)
            #pragma unroll
            for (int r = 0; r < 4; r++) acc[i][j][r] = 0.f;

    for (int k0 = 0; k0 < C; k0 += 16) {
        #pragma unroll
        for (int s = 0; s < 2; s++) {
            int jdx = t + s * 256;
            int kk = jdx >> 5, nn = (jdx & 31) * 4;
            float4 v = *(const float4*)&A[(size_t)(k0 + kk) * N + n0 + nn];
            uint4 u = {f2tf(v.x), f2tf(v.y), f2tf(v.z), f2tf(v.w)};
            *(uint4*)&As[kk * 136 + nn] = u;
        }
        #pragma unroll
        for (int s = 0; s < 2; s++) {
            int jdx = t + s * 256;
            int oo = jdx >> 2, k4 = (jdx & 3) * 4;
            float4 v = *(const float4*)&Wp[(size_t)(c0 + oo) * C + k0 + k4];
            Bs[(k4 + 0) * 136 + oo] = f2tf(v.x);
            Bs[(k4 + 1) * 136 + oo] = f2tf(v.y);
            Bs[(k4 + 2) * 136 + oo] = f2tf(v.z);
            Bs[(k4 + 3) * 136 + oo] = f2tf(v.w);
        }
        __syncthreads();
        #pragma unroll
        for (int ks = 0; ks < 2; ks++) {
            const int kk = ks * 8;
            uint32_t a[4][4], bb[4][2];
            #pragma unroll
            for (int i = 0; i < 4; i++) {
                const uint32_t* p = &As[(kk + tg) * 136 + wm * 64 + i * 16 + g];
                a[i][0] = p[0]; a[i][1] = p[8];
                a[i][2] = p[4 * 136]; a[i][3] = p[4 * 136 + 8];
            }
            #pragma unroll
            for (int j = 0; j < 4; j++) {
                const uint32_t* p = &Bs[(kk + tg) * 136 + wn * 32 + j * 8 + g];
                bb[j][0] = p[0]; bb[j][1] = p[4 * 136];
            }
            #pragma unroll
            for (int i = 0; i < 4; i++)
                #pragma unroll
                for (int j = 0; j < 4; j++) mma8(acc[i][j], a[i], bb[j]);
        }
        __syncthreads();
    }

    #pragma unroll
    for (int j = 0; j < 4; j++) {
        const int co = c0 + wn * 32 + j * 8 + 2 * tg;
        const float b0v = bp[co], b1v = bp[co + 1];
        float* r0 = out + ((size_t)b * C + co) * N;
        float* r1 = out + ((size_t)b * C + co + 1) * N;
        #pragma unroll
        for (int i = 0; i < 4; i++) {
            const int n1 = n0 + wm * 64 + i * 16 + g;
            r0[n1]     = acc[i][j][0] + b0v;
            r1[n1]     = acc[i][j][1] + b1v;
            r0[n1 + 8] = acc[i][j][2] + b0v;
            r1[n1 + 8] = acc[i][j][3] + b1v;
        }
    }
}

// ---------------------------------------------------------------------------
extern "C" void kernel_launch(void* const* d_in, const int* in_sizes, int n_in,
                              void* d_out, int out_size) {
    (void)in_sizes; (void)n_in; (void)out_size;
    const float* x    = (const float*)d_in[0];
    const float* Wqkv = (const float*)d_in[1];
    const float* bqkv = (const float*)d_in[2];
    const float* Wp   = (const float*)d_in[3];
    const float* bp   = (const float*)d_in[4];
    float* out = (float*)d_out;

    const int attn_smem = (4 * 64 * 68 + 64 * 3 + 128 * 2) * (int)sizeof(float); // 71,424 B
    cudaFuncSetAttribute(attn_kernel,
                         cudaFuncAttributeMaxDynamicSharedMemorySize, attn_smem);

    qkv_kernel<<<dim3(8, 12, Bz), 256>>>(x, Wqkv, bqkv);
    attn_kernel<<<dim3(16, 64), 128, attn_smem>>>();
    proj_kernel<<<dim3(8, 4, Bz), 256>>>(Wp, bp, out);
}

// round 6
// speedup vs baseline: 3.7321x; 1.5652x over previous
#include <cuda_runtime.h>
#include <cstdint>

#define Bz 8
#define C  512
#define NH 8
#define HD 64
#define N  1024   /* 32*32 */
#define SMSCALE 0.18033688011112042f   /* 0.125 * log2(e) */

// Scratch: q/k/v (b,h,n,d) and attention output TRANSPOSED (b,c,n).
// All four hold tf32-pre-rounded fp32 bit patterns (consumed only by tf32 MMA).
__device__ float g_q[Bz*NH*N*HD];
__device__ float g_k[Bz*NH*N*HD];
__device__ float g_v[Bz*NH*N*HD];
__device__ float g_ao[Bz*C*N];

// ---------------------------------------------------------------------------
__device__ __forceinline__ uint32_t f2tf(float f) {
    uint32_t r;
    asm("cvt.rna.tf32.f32 %0, %1;" : "=r"(r) : "f"(f));
    return r;
}
__device__ __forceinline__ uint32_t u2tf(uint32_t u) { return f2tf(__uint_as_float(u)); }
__device__ __forceinline__ float ex2(float x) {
    float r;
    asm("ex2.approx.ftz.f32 %0, %1;" : "=f"(r) : "f"(x));
    return r;
}
__device__ __forceinline__ void mma8(float* c, const uint32_t* a, const uint32_t* b) {
    asm volatile(
        "mma.sync.aligned.m16n8k8.row.col.f32.tf32.tf32.f32 "
        "{%0,%1,%2,%3}, {%4,%5,%6,%7}, {%8,%9}, {%0,%1,%2,%3};"
        : "+f"(c[0]), "+f"(c[1]), "+f"(c[2]), "+f"(c[3])
        : "r"(a[0]), "r"(a[1]), "r"(a[2]), "r"(a[3]), "r"(b[0]), "r"(b[1]));
}
__device__ __forceinline__ void cp16(uint32_t d, const void* s) {
    asm volatile("cp.async.cg.shared.global [%0], [%1], 16;" :: "r"(d), "l"(s));
}
__device__ __forceinline__ void cp_commit() { asm volatile("cp.async.commit_group;"); }
__device__ __forceinline__ void cp_wait0() { asm volatile("cp.async.wait_group 0;"); }

// ---------------------------------------------------------------------------
// Kernel 1: qkv = x_seq @ W_qkv^T + b_qkv.  Block tile 128(m) x 128(o), BK=16,
// cp.async double-buffered. A smem [k][m] stride 136; B smem natural [o][k]
// stride 20 (col-major fragment reads conflict-free). tf32 cvt at frag load.
// ---------------------------------------------------------------------------
__global__ __launch_bounds__(256) void qkv_kernel(const float* __restrict__ x,
                                                  const float* __restrict__ Wqkv,
                                                  const float* __restrict__ bqkv) {
    __shared__ uint32_t As[2][16 * 136];
    __shared__ uint32_t Bs[2][128 * 20];
    const int b  = blockIdx.z;
    const int n0 = blockIdx.x * 128;
    const int o0 = blockIdx.y * 128;
    const int t = threadIdx.x, w = t >> 5, lane = t & 31;
    const int g = lane >> 2, tg = lane & 3;
    const int wm = w & 1, wn = w >> 1;
    const float* xb = x + (size_t)b * C * N;
    const uint32_t asb = (uint32_t)__cvta_generic_to_shared(As);
    const uint32_t bsb = (uint32_t)__cvta_generic_to_shared(Bs);

    float acc[4][4][4] = {};

    auto load_stage = [&](int i) {
        const int k0 = i * 16, buf = i & 1;
        const uint32_t ab = asb + buf * (16 * 136 * 4);
        const uint32_t bb = bsb + buf * (128 * 20 * 4);
        #pragma unroll
        for (int s = 0; s < 2; s++) {
            int idx = t + s * 256;
            int kk = idx >> 5, col = (idx & 31) * 4;
            cp16(ab + (kk * 136 + col) * 4, xb + (size_t)(k0 + kk) * N + n0 + col);
        }
        #pragma unroll
        for (int s = 0; s < 2; s++) {
            int idx = t + s * 256;
            int oo = idx >> 2, k4 = (idx & 3) * 4;
            cp16(bb + (oo * 20 + k4) * 4, Wqkv + (size_t)(o0 + oo) * C + k0 + k4);
        }
    };

    load_stage(0); cp_commit();
    for (int i = 0; i < 32; i++) {
        cp_wait0(); __syncthreads();
        if (i + 1 < 32) { load_stage(i + 1); cp_commit(); }
        const uint32_t* Ab = As[i & 1];
        const uint32_t* Bb = Bs[i & 1];
        #pragma unroll
        for (int ks = 0; ks < 2; ks++) {
            const int kk = ks * 8;
            uint32_t a[4][4], bv[4][2];
            #pragma unroll
            for (int ii = 0; ii < 4; ii++) {
                const uint32_t* p = &Ab[(kk + tg) * 136 + wm * 64 + ii * 16 + g];
                a[ii][0] = u2tf(p[0]);       a[ii][1] = u2tf(p[8]);
                a[ii][2] = u2tf(p[4 * 136]); a[ii][3] = u2tf(p[4 * 136 + 8]);
            }
            #pragma unroll
            for (int j = 0; j < 4; j++) {
                const uint32_t* p = &Bb[(wn * 32 + j * 8 + g) * 20 + kk + tg];
                bv[j][0] = u2tf(p[0]); bv[j][1] = u2tf(p[4]);
            }
            #pragma unroll
            for (int ii = 0; ii < 4; ii++)
                #pragma unroll
                for (int j = 0; j < 4; j++) mma8(acc[ii][j], a[ii], bv[j]);
        }
    }

    // Epilogue: scatter tf32-rounded q/k/v (b,h,n,d).
    const int three = o0 >> 9;
    float* base = (three == 0 ? g_q : (three == 1 ? g_k : g_v));
    #pragma unroll
    for (int j = 0; j < 4; j++) {
        const int o = o0 + wn * 32 + j * 8 + 2 * tg;
        const int h = (o >> 6) & 7, d = o & 63;
        const float b0v = bqkv[o], b1v = bqkv[o + 1];
        float* dsth = base + ((size_t)(b * NH + h) * N) * HD + d;
        #pragma unroll
        for (int i = 0; i < 4; i++) {
            const int n1 = n0 + wm * 64 + i * 16 + g;
            float2 v0 = {__uint_as_float(f2tf(acc[i][j][0] + b0v)),
                         __uint_as_float(f2tf(acc[i][j][1] + b1v))};
            float2 v1 = {__uint_as_float(f2tf(acc[i][j][2] + b0v)),
                         __uint_as_float(f2tf(acc[i][j][3] + b1v))};
            *(float2*)&dsth[(size_t)n1 * HD]       = v0;
            *(float2*)&dsth[(size_t)(n1 + 8) * HD] = v1;
        }
    }
}

// ---------------------------------------------------------------------------
// Kernel 2: causal flash attention. 4 warps, 64 q-rows, 64-wide KV tiles,
// cp.async double-buffered KV (raw, pre-rounded tf32 — zero cvts in loop).
// Softmax state in registers; row reductions via shfl; P staged to warp-
// private smem (syncwarp only). ONE __syncthreads per KV tile.
// ---------------------------------------------------------------------------
extern __shared__ uint32_t sm_u[];

__global__ __launch_bounds__(128) void attn_kernel() {
    uint32_t* Qs = sm_u;                 // [64][68]
    uint32_t* Ks = Qs + 64 * 68;         // 2 x [64][68] natural [kpos][d]
    uint32_t* Vs = Ks + 2 * 64 * 68;     // 2 x [64][72] natural [kpos][d]
    uint32_t* Sf = Vs + 2 * 64 * 72;     // [64][68] P (tf32), warp-private rows

    const int qt = 15 - (int)blockIdx.x;     // heavy blocks first
    const int bh = blockIdx.y;
    const int n0 = qt * 64;
    const float* Q = g_q + (size_t)bh * N * HD;
    const float* K = g_k + (size_t)bh * N * HD;
    const float* V = g_v + (size_t)bh * N * HD;

    const int t = threadIdx.x, w = t >> 5, lane = t & 31;
    const int g = lane >> 2, tg = lane & 3;
    const int m0 = w * 16;
    const uint32_t qsb = (uint32_t)__cvta_generic_to_shared(Qs);
    const uint32_t ksb = (uint32_t)__cvta_generic_to_shared(Ks);
    const uint32_t vsb = (uint32_t)__cvta_generic_to_shared(Vs);

    #pragma unroll
    for (int it = 0; it < 8; it++) {
        int idx = t + it * 128;
        int row = idx >> 4, col = (idx & 15) * 4;
        cp16(qsb + (row * 68 + col) * 4, Q + (size_t)(n0 + row) * HD + col);
    }
    auto load_kv = [&](int kt) {
        const int k0 = kt * 64, buf = kt & 1;
        #pragma unroll
        for (int it = 0; it < 8; it++) {
            int idx = t + it * 128;
            int row = idx >> 4, col = (idx & 15) * 4;
            cp16(ksb + (buf * (64 * 68) + row * 68 + col) * 4, K + (size_t)(k0 + row) * HD + col);
            cp16(vsb + (buf * (64 * 72) + row * 72 + col) * 4, V + (size_t)(k0 + row) * HD + col);
        }
    };
    load_kv(0); cp_commit();

    float mr0 = -1e30f, mr1 = -1e30f, l0 = 0.f, l1 = 0.f;
    float o[8][4] = {};

    for (int kt = 0; kt <= qt; kt++) {
        cp_wait0(); __syncthreads();
        if (kt < qt) { load_kv(kt + 1); cp_commit(); }
        const uint32_t* kb = Ks + (kt & 1) * (64 * 68);
        const uint32_t* vb = Vs + (kt & 1) * (64 * 72);

        // ---- Phase 1: S = Q K^T ----
        float s[8][4] = {};
        #pragma unroll
        for (int ks = 0; ks < 8; ks++) {
            const int kk = ks * 8;
            uint32_t a[4];
            const uint32_t* pa = &Qs[(m0 + g) * 68 + kk + tg];
            a[0] = pa[0]; a[1] = pa[8 * 68]; a[2] = pa[4]; a[3] = pa[8 * 68 + 4];
            #pragma unroll
            for (int j = 0; j < 8; j++) {
                uint32_t bb2[2];
                const uint32_t* pb = &kb[(j * 8 + g) * 68 + kk + tg];
                bb2[0] = pb[0]; bb2[1] = pb[4];
                mma8(s[j], a, bb2);
            }
        }

        if (kt == qt) {   // causal mask, diagonal tile only
            #pragma unroll
            for (int j = 0; j < 8; j++) {
                const int c0 = j * 8 + 2 * tg;
                if (c0     > m0 + g)     s[j][0] = -1e30f;
                if (c0 + 1 > m0 + g)     s[j][1] = -1e30f;
                if (c0     > m0 + g + 8) s[j][2] = -1e30f;
                if (c0 + 1 > m0 + g + 8) s[j][3] = -1e30f;
            }
        }

        // ---- softmax, all in registers (quad 4g..4g+3 owns rows g, g+8) ----
        float mx0 = -1e30f, mx1 = -1e30f;
        #pragma unroll
        for (int j = 0; j < 8; j++) {
            mx0 = fmaxf(mx0, fmaxf(s[j][0], s[j][1]));
            mx1 = fmaxf(mx1, fmaxf(s[j][2], s[j][3]));
        }
        mx0 = fmaxf(mx0, __shfl_xor_sync(0xffffffffu, mx0, 1));
        mx0 = fmaxf(mx0, __shfl_xor_sync(0xffffffffu, mx0, 2));
        mx1 = fmaxf(mx1, __shfl_xor_sync(0xffffffffu, mx1, 1));
        mx1 = fmaxf(mx1, __shfl_xor_sync(0xffffffffu, mx1, 2));
        const float mn0 = fmaxf(mr0, mx0 * SMSCALE);
        const float mn1 = fmaxf(mr1, mx1 * SMSCALE);
        const float f0 = ex2(mr0 - mn0), f1 = ex2(mr1 - mn1);
        mr0 = mn0; mr1 = mn1;

        float sum0 = 0.f, sum1 = 0.f;
        uint32_t* sp0 = &Sf[(m0 + g) * 68 + 2 * tg];
        uint32_t* sp1 = sp0 + 8 * 68;
        #pragma unroll
        for (int j = 0; j < 8; j++) {
            float p0 = ex2(s[j][0] * SMSCALE - mn0);
            float p1 = ex2(s[j][1] * SMSCALE - mn0);
            float p2 = ex2(s[j][2] * SMSCALE - mn1);
            float p3 = ex2(s[j][3] * SMSCALE - mn1);
            sum0 += p0 + p1; sum1 += p2 + p3;
            sp0[j * 8] = f2tf(p0); sp0[j * 8 + 1] = f2tf(p1);
            sp1[j * 8] = f2tf(p2); sp1[j * 8 + 1] = f2tf(p3);
        }
        sum0 += __shfl_xor_sync(0xffffffffu, sum0, 1);
        sum0 += __shfl_xor_sync(0xffffffffu, sum0, 2);
        sum1 += __shfl_xor_sync(0xffffffffu, sum1, 1);
        sum1 += __shfl_xor_sync(0xffffffffu, sum1, 2);
        l0 = l0 * f0 + sum0;
        l1 = l1 * f1 + sum1;
        __syncwarp();

        #pragma unroll
        for (int j = 0; j < 8; j++) {
            o[j][0] *= f0; o[j][1] *= f0; o[j][2] *= f1; o[j][3] *= f1;
        }
        // ---- Phase 2: O += P V ----
        #pragma unroll
        for (int ks = 0; ks < 8; ks++) {
            const int kk = ks * 8;
            uint32_t a[4];
            const uint32_t* pa = &Sf[(m0 + g) * 68 + kk + tg];
            a[0] = pa[0]; a[1] = pa[8 * 68]; a[2] = pa[4]; a[3] = pa[8 * 68 + 4];
            #pragma unroll
            for (int j = 0; j < 8; j++) {
                uint32_t bb2[2];
                const uint32_t* pb = &vb[(kk + tg) * 72 + j * 8 + g];
                bb2[0] = pb[0]; bb2[1] = pb[4 * 72];
                mma8(o[j], a, bb2);
            }
        }
    }

    // Epilogue: write aoT [b][cfeat][n], tf32-rounded (feeds proj tf32 MMA).
    const float inv0 = 1.f / l0, inv1 = 1.f / l1;
    const int b = bh >> 3, h = bh & 7;
    float* ao = g_ao + (size_t)b * C * N + (size_t)h * 64 * N;
    const int n1 = n0 + m0 + g;
    #pragma unroll
    for (int j = 0; j < 8; j++) {
        const int d = j * 8 + 2 * tg;
        ao[(size_t)d * N + n1]           = __uint_as_float(f2tf(o[j][0] * inv0));
        ao[(size_t)(d + 1) * N + n1]     = __uint_as_float(f2tf(o[j][1] * inv0));
        ao[(size_t)d * N + n1 + 8]       = __uint_as_float(f2tf(o[j][2] * inv1));
        ao[(size_t)(d + 1) * N + n1 + 8] = __uint_as_float(f2tf(o[j][3] * inv1));
    }
}

// ---------------------------------------------------------------------------
// Kernel 3: out[b][co][n] = aoT[b][:,n] @ W_proj[co][:] + b_proj[co].
// Same pipeline as qkv; A (g_ao) is pre-rounded -> no cvt on A fragments.
// ---------------------------------------------------------------------------
__global__ __launch_bounds__(256) void proj_kernel(const float* __restrict__ Wp,
                                                   const float* __restrict__ bp,
                                                   float* __restrict__ out) {
    __shared__ uint32_t As[2][16 * 136];
    __shared__ uint32_t Bs[2][128 * 20];
    const int b  = blockIdx.z;
    const int n0 = blockIdx.x * 128;
    const int c0 = blockIdx.y * 128;
    const int t = threadIdx.x, w = t >> 5, lane = t & 31;
    const int g = lane >> 2, tg = lane & 3;
    const int wm = w & 1, wn = w >> 1;
    const float* A = g_ao + (size_t)b * C * N;
    const uint32_t asb = (uint32_t)__cvta_generic_to_shared(As);
    const uint32_t bsb = (uint32_t)__cvta_generic_to_shared(Bs);

    float acc[4][4][4] = {};

    auto load_stage = [&](int i) {
        const int k0 = i * 16, buf = i & 1;
        const uint32_t ab = asb + buf * (16 * 136 * 4);
        const uint32_t bb = bsb + buf * (128 * 20 * 4);
        #pragma unroll
        for (int s = 0; s < 2; s++) {
            int idx = t + s * 256;
            int kk = idx >> 5, col = (idx & 31) * 4;
            cp16(ab + (kk * 136 + col) * 4, A + (size_t)(k0 + kk) * N + n0 + col);
        }
        #pragma unroll
        for (int s = 0; s < 2; s++) {
            int idx = t + s * 256;
            int oo = idx >> 2, k4 = (idx & 3) * 4;
            cp16(bb + (oo * 20 + k4) * 4, Wp + (size_t)(c0 + oo) * C + k0 + k4);
        }
    };

    load_stage(0); cp_commit();
    for (int i = 0; i < 32; i++) {
        cp_wait0(); __syncthreads();
        if (i + 1 < 32) { load_stage(i + 1); cp_commit(); }
        const uint32_t* Ab = As[i & 1];
        const uint32_t* Bb = Bs[i & 1];
        #pragma unroll
        for (int ks = 0; ks < 2; ks++) {
            const int kk = ks * 8;
            uint32_t a[4][4], bv[4][2];
            #pragma unroll
            for (int ii = 0; ii < 4; ii++) {
                const uint32_t* p = &Ab[(kk + tg) * 136 + wm * 64 + ii * 16 + g];
                a[ii][0] = p[0];       a[ii][1] = p[8];
                a[ii][2] = p[4 * 136]; a[ii][3] = p[4 * 136 + 8];
            }
            #pragma unroll
            for (int j = 0; j < 4; j++) {
                const uint32_t* p = &Bb[(wn * 32 + j * 8 + g) * 20 + kk + tg];
                bv[j][0] = u2tf(p[0]); bv[j][1] = u2tf(p[4]);
            }
            #pragma unroll
            for (int ii = 0; ii < 4; ii++)
                #pragma unroll
                for (int j = 0; j < 4; j++) mma8(acc[ii][j], a[ii], bv[j]);
        }
    }

    #pragma unroll
    for (int j = 0; j < 4; j++) {
        const int co = c0 + wn * 32 + j * 8 + 2 * tg;
        const float b0v = bp[co], b1v = bp[co + 1];
        float* r0 = out + ((size_t)b * C + co) * N;
        float* r1 = out + ((size_t)b * C + co + 1) * N;
        #pragma unroll
        for (int i = 0; i < 4; i++) {
            const int n1 = n0 + wm * 64 + i * 16 + g;
            r0[n1]     = acc[i][j][0] + b0v;
            r1[n1]     = acc[i][j][1] + b1v;
            r0[n1 + 8] = acc[i][j][2] + b0v;
            r1[n1 + 8] = acc[i][j][3] + b1v;
        }
    }
}

// ---------------------------------------------------------------------------
extern "C" void kernel_launch(void* const* d_in, const int* in_sizes, int n_in,
                              void* d_out, int out_size) {
    (void)in_sizes; (void)n_in; (void)out_size;
    const float* x    = (const float*)d_in[0];
    const float* Wqkv = (const float*)d_in[1];
    const float* bqkv = (const float*)d_in[2];
    const float* Wp   = (const float*)d_in[3];
    const float* bp   = (const float*)d_in[4];
    float* out = (float*)d_out;

    const int attn_smem = (64*68 + 2*64*68 + 2*64*72 + 64*68) * (int)sizeof(uint32_t); // 106,496 B
    cudaFuncSetAttribute(attn_kernel,
                         cudaFuncAttributeMaxDynamicSharedMemorySize, attn_smem);

    qkv_kernel<<<dim3(8, 12, Bz), 256>>>(x, Wqkv, bqkv);
    attn_kernel<<<dim3(16, 64), 128, attn_smem>>>();
    proj_kernel<<<dim3(8, 4, Bz), 256>>>(Wp, bp, out);
}

// round 10
// speedup vs baseline: 3.7533x; 1.0057x over previous
#include <cuda_runtime.h>
#include <cstdint>

#define Bz 8
#define C  512
#define NH 8
#define HD 64
#define N  1024   /* 32*32 */
#define SMSCALE 0.18033688011112042f   /* 0.125 * log2(e) */

// Scratch: q/k/v (b,h,n,d) and attention output TRANSPOSED (b,c,n).
// All hold tf32-pre-rounded fp32 bit patterns (consumed only by tf32 MMA).
__device__ float g_q[Bz*NH*N*HD];
__device__ float g_k[Bz*NH*N*HD];
__device__ float g_v[Bz*NH*N*HD];
__device__ float g_ao[Bz*C*N];
// Pre-rounded inputs (same layouts as the originals).
__device__ float g_xr [Bz*C*N];
__device__ float g_wqr[3*C*C];
__device__ float g_wpr[C*C];

// ---------------------------------------------------------------------------
__device__ __forceinline__ uint32_t f2tf(float f) {
    uint32_t r;
    asm("cvt.rna.tf32.f32 %0, %1;" : "=r"(r) : "f"(f));
    return r;
}
__device__ __forceinline__ float rnd(float f) { return __uint_as_float(f2tf(f)); }
__device__ __forceinline__ float ex2(float x) {
    float r;
    asm("ex2.approx.ftz.f32 %0, %1;" : "=f"(r) : "f"(x));
    return r;
}
__device__ __forceinline__ void mma8(float* c, const uint32_t* a, const uint32_t* b) {
    asm volatile(
        "mma.sync.aligned.m16n8k8.row.col.f32.tf32.tf32.f32 "
        "{%0,%1,%2,%3}, {%4,%5,%6,%7}, {%8,%9}, {%0,%1,%2,%3};"
        : "+f"(c[0]), "+f"(c[1]), "+f"(c[2]), "+f"(c[3])
        : "r"(a[0]), "r"(a[1]), "r"(a[2]), "r"(a[3]), "r"(b[0]), "r"(b[1]));
}
__device__ __forceinline__ void cp16(uint32_t d, const void* s) {
    asm volatile("cp.async.cg.shared.global [%0], [%1], 16;" :: "r"(d), "l"(s));
}
__device__ __forceinline__ void cp_commit() { asm volatile("cp.async.commit_group;"); }
__device__ __forceinline__ void cp_wait0() { asm volatile("cp.async.wait_group 0;"); }

// ---------------------------------------------------------------------------
// Prepass: elementwise tf32 round into a __device__ global selected in DEVICE
// code (host code must never take the address of a __device__ symbol — that
// was the R7/R8 failure).
__global__ __launch_bounds__(256) void round_kernel(const float4* __restrict__ src,
                                                    int which) {
    float4* dst = (which == 0) ? (float4*)g_xr
                : (which == 1) ? (float4*)g_wqr
                               : (float4*)g_wpr;
    int i = blockIdx.x * 256 + threadIdx.x;
    float4 v = src[i];
    v.x = rnd(v.x); v.y = rnd(v.y); v.z = rnd(v.z); v.w = rnd(v.w);
    dst[i] = v;
}

// ---------------------------------------------------------------------------
// Kernel 1: qkv = x_seq @ W_qkv^T + b_qkv.  Block tile 128(m) x 128(o), BK=16,
// cp.async double-buffered. A smem [k][m] stride 136; B smem natural [o][k]
// stride 20. Inputs pre-rounded -> ZERO cvts in the mainloop.
// ---------------------------------------------------------------------------
__global__ __launch_bounds__(256) void qkv_kernel(const float* __restrict__ bqkv) {
    __shared__ uint32_t As[2][16 * 136];
    __shared__ uint32_t Bs[2][128 * 20];
    const int b  = blockIdx.z;
    const int n0 = blockIdx.x * 128;
    const int o0 = blockIdx.y * 128;
    const int t = threadIdx.x, w = t >> 5, lane = t & 31;
    const int g = lane >> 2, tg = lane & 3;
    const int wm = w & 1, wn = w >> 1;
    const float* xb = g_xr + (size_t)b * C * N;
    const uint32_t asb = (uint32_t)__cvta_generic_to_shared(As);
    const uint32_t bsb = (uint32_t)__cvta_generic_to_shared(Bs);

    float acc[4][4][4] = {};

    auto load_stage = [&](int i) {
        const int k0 = i * 16, buf = i & 1;
        const uint32_t ab = asb + buf * (16 * 136 * 4);
        const uint32_t bb = bsb + buf * (128 * 20 * 4);
        #pragma unroll
        for (int s = 0; s < 2; s++) {
            int idx = t + s * 256;
            int kk = idx >> 5, col = (idx & 31) * 4;
            cp16(ab + (kk * 136 + col) * 4, xb + (size_t)(k0 + kk) * N + n0 + col);
        }
        #pragma unroll
        for (int s = 0; s < 2; s++) {
            int idx = t + s * 256;
            int oo = idx >> 2, k4 = (idx & 3) * 4;
            cp16(bb + (oo * 20 + k4) * 4, g_wqr + (size_t)(o0 + oo) * C + k0 + k4);
        }
    };

    load_stage(0); cp_commit();
    for (int i = 0; i < 32; i++) {
        cp_wait0(); __syncthreads();
        if (i + 1 < 32) { load_stage(i + 1); cp_commit(); }
        const uint32_t* Ab = As[i & 1];
        const uint32_t* Bb = Bs[i & 1];
        #pragma unroll
        for (int ks = 0; ks < 2; ks++) {
            const int kk = ks * 8;
            uint32_t a[4][4], bv[4][2];
            #pragma unroll
            for (int ii = 0; ii < 4; ii++) {
                const uint32_t* p = &Ab[(kk + tg) * 136 + wm * 64 + ii * 16 + g];
                a[ii][0] = p[0];       a[ii][1] = p[8];
                a[ii][2] = p[4 * 136]; a[ii][3] = p[4 * 136 + 8];
            }
            #pragma unroll
            for (int j = 0; j < 4; j++) {
                const uint32_t* p = &Bb[(wn * 32 + j * 8 + g) * 20 + kk + tg];
                bv[j][0] = p[0]; bv[j][1] = p[4];
            }
            #pragma unroll
            for (int ii = 0; ii < 4; ii++)
                #pragma unroll
                for (int j = 0; j < 4; j++) mma8(acc[ii][j], a[ii], bv[j]);
        }
    }

    // Epilogue: scatter tf32-rounded q/k/v (b,h,n,d).
    const int three = o0 >> 9;
    float* base = (three == 0 ? g_q : (three == 1 ? g_k : g_v));
    #pragma unroll
    for (int j = 0; j < 4; j++) {
        const int o = o0 + wn * 32 + j * 8 + 2 * tg;
        const int h = (o >> 6) & 7, d = o & 63;
        const float b0v = bqkv[o], b1v = bqkv[o + 1];
        float* dsth = base + ((size_t)(b * NH + h) * N) * HD + d;
        #pragma unroll
        for (int i = 0; i < 4; i++) {
            const int n1 = n0 + wm * 64 + i * 16 + g;
            float2 v0 = {rnd(acc[i][j][0] + b0v), rnd(acc[i][j][1] + b1v)};
            float2 v1 = {rnd(acc[i][j][2] + b0v), rnd(acc[i][j][3] + b1v)};
            *(float2*)&dsth[(size_t)n1 * HD]       = v0;
            *(float2*)&dsth[(size_t)(n1 + 8) * HD] = v1;
        }
    }
}

// ---------------------------------------------------------------------------
// Kernel 2: causal flash attention (unchanged from R6 known-good).
// ---------------------------------------------------------------------------
extern __shared__ uint32_t sm_u[];

__global__ __launch_bounds__(128) void attn_kernel() {
    uint32_t* Qs = sm_u;                 // [64][68]
    uint32_t* Ks = Qs + 64 * 68;         // 2 x [64][68] natural [kpos][d]
    uint32_t* Vs = Ks + 2 * 64 * 68;     // 2 x [64][72] natural [kpos][d]
    uint32_t* Sf = Vs + 2 * 64 * 72;     // [64][68] P (tf32), warp-private rows

    const int qt = 15 - (int)blockIdx.x; // heavy blocks first
    const int bh = blockIdx.y;
    const int n0 = qt * 64;
    const float* Q = g_q + (size_t)bh * N * HD;
    const float* K = g_k + (size_t)bh * N * HD;
    const float* V = g_v + (size_t)bh * N * HD;

    const int t = threadIdx.x, w = t >> 5, lane = t & 31;
    const int g = lane >> 2, tg = lane & 3;
    const int m0 = w * 16;
    const uint32_t qsb = (uint32_t)__cvta_generic_to_shared(Qs);
    const uint32_t ksb = (uint32_t)__cvta_generic_to_shared(Ks);
    const uint32_t vsb = (uint32_t)__cvta_generic_to_shared(Vs);

    #pragma unroll
    for (int it = 0; it < 8; it++) {
        int idx = t + it * 128;
        int row = idx >> 4, col = (idx & 15) * 4;
        cp16(qsb + (row * 68 + col) * 4, Q + (size_t)(n0 + row) * HD + col);
    }
    auto load_kv = [&](int kt) {
        const int k0 = kt * 64, buf = kt & 1;
        #pragma unroll
        for (int it = 0; it < 8; it++) {
            int idx = t + it * 128;
            int row = idx >> 4, col = (idx & 15) * 4;
            cp16(ksb + (buf * (64 * 68) + row * 68 + col) * 4, K + (size_t)(k0 + row) * HD + col);
            cp16(vsb + (buf * (64 * 72) + row * 72 + col) * 4, V + (size_t)(k0 + row) * HD + col);
        }
    };
    load_kv(0); cp_commit();

    float mr0 = -1e30f, mr1 = -1e30f, l0 = 0.f, l1 = 0.f;
    float o[8][4] = {};

    for (int kt = 0; kt <= qt; kt++) {
        cp_wait0(); __syncthreads();
        if (kt < qt) { load_kv(kt + 1); cp_commit(); }
        const uint32_t* kb = Ks + (kt & 1) * (64 * 68);
        const uint32_t* vb = Vs + (kt & 1) * (64 * 72);

        // ---- Phase 1: S = Q K^T ----
        float s[8][4] = {};
        #pragma unroll
        for (int ks = 0; ks < 8; ks++) {
            const int kk = ks * 8;
            uint32_t a[4];
            const uint32_t* pa = &Qs[(m0 + g) * 68 + kk + tg];
            a[0] = pa[0]; a[1] = pa[8 * 68]; a[2] = pa[4]; a[3] = pa[8 * 68 + 4];
            #pragma unroll
            for (int j = 0; j < 8; j++) {
                uint32_t bb2[2];
                const uint32_t* pb = &kb[(j * 8 + g) * 68 + kk + tg];
                bb2[0] = pb[0]; bb2[1] = pb[4];
                mma8(s[j], a, bb2);
            }
        }

        if (kt == qt) {   // causal mask, diagonal tile only
            #pragma unroll
            for (int j = 0; j < 8; j++) {
                const int c0 = j * 8 + 2 * tg;
                if (c0     > m0 + g)     s[j][0] = -1e30f;
                if (c0 + 1 > m0 + g)     s[j][1] = -1e30f;
                if (c0     > m0 + g + 8) s[j][2] = -1e30f;
                if (c0 + 1 > m0 + g + 8) s[j][3] = -1e30f;
            }
        }

        // ---- softmax in registers (quad owns rows g, g+8) ----
        float mx0 = -1e30f, mx1 = -1e30f;
        #pragma unroll
        for (int j = 0; j < 8; j++) {
            mx0 = fmaxf(mx0, fmaxf(s[j][0], s[j][1]));
            mx1 = fmaxf(mx1, fmaxf(s[j][2], s[j][3]));
        }
        mx0 = fmaxf(mx0, __shfl_xor_sync(0xffffffffu, mx0, 1));
        mx0 = fmaxf(mx0, __shfl_xor_sync(0xffffffffu, mx0, 2));
        mx1 = fmaxf(mx1, __shfl_xor_sync(0xffffffffu, mx1, 1));
        mx1 = fmaxf(mx1, __shfl_xor_sync(0xffffffffu, mx1, 2));
        const float mn0 = fmaxf(mr0, mx0 * SMSCALE);
        const float mn1 = fmaxf(mr1, mx1 * SMSCALE);
        const float f0 = ex2(mr0 - mn0), f1 = ex2(mr1 - mn1);
        mr0 = mn0; mr1 = mn1;

        float sum0 = 0.f, sum1 = 0.f;
        uint32_t* sp0 = &Sf[(m0 + g) * 68 + 2 * tg];
        uint32_t* sp1 = sp0 + 8 * 68;
        #pragma unroll
        for (int j = 0; j < 8; j++) {
            float p0 = ex2(s[j][0] * SMSCALE - mn0);
            float p1 = ex2(s[j][1] * SMSCALE - mn0);
            float p2 = ex2(s[j][2] * SMSCALE - mn1);
            float p3 = ex2(s[j][3] * SMSCALE - mn1);
            sum0 += p0 + p1; sum1 += p2 + p3;
            sp0[j * 8] = f2tf(p0); sp0[j * 8 + 1] = f2tf(p1);
            sp1[j * 8] = f2tf(p2); sp1[j * 8 + 1] = f2tf(p3);
        }
        sum0 += __shfl_xor_sync(0xffffffffu, sum0, 1);
        sum0 += __shfl_xor_sync(0xffffffffu, sum0, 2);
        sum1 += __shfl_xor_sync(0xffffffffu, sum1, 1);
        sum1 += __shfl_xor_sync(0xffffffffu, sum1, 2);
        l0 = l0 * f0 + sum0;
        l1 = l1 * f1 + sum1;
        __syncwarp();

        #pragma unroll
        for (int j = 0; j < 8; j++) {
            o[j][0] *= f0; o[j][1] *= f0; o[j][2] *= f1; o[j][3] *= f1;
        }
        // ---- Phase 2: O += P V ----
        #pragma unroll
        for (int ks = 0; ks < 8; ks++) {
            const int kk = ks * 8;
            uint32_t a[4];
            const uint32_t* pa = &Sf[(m0 + g) * 68 + kk + tg];
            a[0] = pa[0]; a[1] = pa[8 * 68]; a[2] = pa[4]; a[3] = pa[8 * 68 + 4];
            #pragma unroll
            for (int j = 0; j < 8; j++) {
                uint32_t bb2[2];
                const uint32_t* pb = &vb[(kk + tg) * 72 + j * 8 + g];
                bb2[0] = pb[0]; bb2[1] = pb[4 * 72];
                mma8(o[j], a, bb2);
            }
        }
    }

    // Epilogue: write aoT [b][cfeat][n], tf32-rounded (feeds proj tf32 MMA).
    const float inv0 = 1.f / l0, inv1 = 1.f / l1;
    const int b = bh >> 3, h = bh & 7;
    float* ao = g_ao + (size_t)b * C * N + (size_t)h * 64 * N;
    const int n1 = n0 + m0 + g;
    #pragma unroll
    for (int j = 0; j < 8; j++) {
        const int d = j * 8 + 2 * tg;
        ao[(size_t)d * N + n1]           = rnd(o[j][0] * inv0);
        ao[(size_t)(d + 1) * N + n1]     = rnd(o[j][1] * inv0);
        ao[(size_t)d * N + n1 + 8]       = rnd(o[j][2] * inv1);
        ao[(size_t)(d + 1) * N + n1 + 8] = rnd(o[j][3] * inv1);
    }
}

// ---------------------------------------------------------------------------
// Kernel 3: out[b][co][n] = aoT[b][:,n] @ W_proj[co][:] + b_proj[co].
// Same pipeline as qkv; both operands pre-rounded -> zero cvts.
// ---------------------------------------------------------------------------
__global__ __launch_bounds__(256) void proj_kernel(const float* __restrict__ bp,
                                                   float* __restrict__ out) {
    __shared__ uint32_t As[2][16 * 136];
    __shared__ uint32_t Bs[2][128 * 20];
    const int b  = blockIdx.z;
    const int n0 = blockIdx.x * 128;
    const int c0 = blockIdx.y * 128;
    const int t = threadIdx.x, w = t >> 5, lane = t & 31;
    const int g = lane >> 2, tg = lane & 3;
    const int wm = w & 1, wn = w >> 1;
    const float* A = g_ao + (size_t)b * C * N;
    const uint32_t asb = (uint32_t)__cvta_generic_to_shared(As);
    const uint32_t bsb = (uint32_t)__cvta_generic_to_shared(Bs);

    float acc[4][4][4] = {};

    auto load_stage = [&](int i) {
        const int k0 = i * 16, buf = i & 1;
        const uint32_t ab = asb + buf * (16 * 136 * 4);
        const uint32_t bb = bsb + buf * (128 * 20 * 4);
        #pragma unroll
        for (int s = 0; s < 2; s++) {
            int idx = t + s * 256;
            int kk = idx >> 5, col = (idx & 31) * 4;
            cp16(ab + (kk * 136 + col) * 4, A + (size_t)(k0 + kk) * N + n0 + col);
        }
        #pragma unroll
        for (int s = 0; s < 2; s++) {
            int idx = t + s * 256;
            int oo = idx >> 2, k4 = (idx & 3) * 4;
            cp16(bb + (oo * 20 + k4) * 4, g_wpr + (size_t)(c0 + oo) * C + k0 + k4);
        }
    };

    load_stage(0); cp_commit();
    for (int i = 0; i < 32; i++) {
        cp_wait0(); __syncthreads();
        if (i + 1 < 32) { load_stage(i + 1); cp_commit(); }
        const uint32_t* Ab = As[i & 1];
        const uint32_t* Bb = Bs[i & 1];
        #pragma unroll
        for (int ks = 0; ks < 2; ks++) {
            const int kk = ks * 8;
            uint32_t a[4][4], bv[4][2];
            #pragma unroll
            for (int ii = 0; ii < 4; ii++) {
                const uint32_t* p = &Ab[(kk + tg) * 136 + wm * 64 + ii * 16 + g];
                a[ii][0] = p[0];       a[ii][1] = p[8];
                a[ii][2] = p[4 * 136]; a[ii][3] = p[4 * 136 + 8];
            }
            #pragma unroll
            for (int j = 0; j < 4; j++) {
                const uint32_t* p = &Bb[(wn * 32 + j * 8 + g) * 20 + kk + tg];
                bv[j][0] = p[0]; bv[j][1] = p[4];
            }
            #pragma unroll
            for (int ii = 0; ii < 4; ii++)
                #pragma unroll
                for (int j = 0; j < 4; j++) mma8(acc[ii][j], a[ii], bv[j]);
        }
    }

    #pragma unroll
    for (int j = 0; j < 4; j++) {
        const int co = c0 + wn * 32 + j * 8 + 2 * tg;
        const float b0v = bp[co], b1v = bp[co + 1];
        float* r0 = out + ((size_t)b * C + co) * N;
        float* r1 = out + ((size_t)b * C + co + 1) * N;
        #pragma unroll
        for (int i = 0; i < 4; i++) {
            const int n1 = n0 + wm * 64 + i * 16 + g;
            r0[n1]     = acc[i][j][0] + b0v;
            r1[n1]     = acc[i][j][1] + b1v;
            r0[n1 + 8] = acc[i][j][2] + b0v;
            r1[n1 + 8] = acc[i][j][3] + b1v;
        }
    }
}

// ---------------------------------------------------------------------------
extern "C" void kernel_launch(void* const* d_in, const int* in_sizes, int n_in,
                              void* d_out, int out_size) {
    (void)in_sizes; (void)n_in; (void)out_size;
    const float* x    = (const float*)d_in[0];
    const float* Wqkv = (const float*)d_in[1];
    const float* bqkv = (const float*)d_in[2];
    const float* Wp   = (const float*)d_in[3];
    const float* bp   = (const float*)d_in[4];
    float* out = (float*)d_out;

    const int attn_smem = (64*68 + 2*64*68 + 2*64*72 + 64*68) * (int)sizeof(uint32_t); // 106,496 B
    cudaFuncSetAttribute(attn_kernel,
                         cudaFuncAttributeMaxDynamicSharedMemorySize, attn_smem);

    round_kernel<<<Bz * C * N / 4 / 256, 256>>>((const float4*)x, 0);
    round_kernel<<<3 * C * C / 4 / 256, 256>>>((const float4*)Wqkv, 1);
    round_kernel<<<C * C / 4 / 256, 256>>>((const float4*)Wp, 2);
    qkv_kernel<<<dim3(8, 12, Bz), 256>>>(bqkv);
    attn_kernel<<<dim3(16, 64), 128, attn_smem>>>();
    proj_kernel<<<dim3(8, 4, Bz), 256>>>(bp, out);
}